// round 4
// baseline (speedup 1.0000x reference)
#include <cuda_runtime.h>
#include <cuda_bf16.h>
#include <cooperative_groups.h>
#include <cstdint>

namespace cg = cooperative_groups;

// Problem dims
#define NUM_C 1024
#define EMB   512
#define HID   512
#define BATCH 64
#define SEQ   512
#define M_ROWS (BATCH * SEQ)   // 32768

// ---------------------------------------------------------------------------
// Device scratch (allocation-free contract: __device__ globals)
// ---------------------------------------------------------------------------
__device__ float g_xproj[(size_t)M_ROWS * HID];   // 64 MB: Wx x + bx + bh
__device__ float g_hs   [(size_t)M_ROWS * HID];   // 64 MB: scan outputs

// ---------------------------------------------------------------------------
// xproj GEMM: out[m][n] = sum_e emb[idx[m]][e] * Wx_w[n][e] + Wx_b[n] + Wh_b[n]
// ---------------------------------------------------------------------------
__global__ __launch_bounds__(256, 2)
void xproj_kernel(const int* __restrict__ q, const int* __restrict__ r,
                  const float* __restrict__ emb,
                  const float* __restrict__ Wx_w,
                  const float* __restrict__ Wx_b,
                  const float* __restrict__ Wh_b) {
    __shared__ float As[8][128];
    __shared__ float Bs[8][128];
    __shared__ int   sidx[128];

    const int tid  = threadIdx.x;
    const int row0 = blockIdx.y * 128;
    const int col0 = blockIdx.x * 128;

    if (tid < 128) {
        int m = row0 + tid;
        sidx[tid] = q[m] + NUM_C * r[m];
    }
    __syncthreads();

    const int lr = tid >> 1;
    const int lc = (tid & 1) * 4;
    const int tx = tid & 15;
    const int ty = tid >> 4;

    const int arow = sidx[lr];

    const float* aptr = emb  + (size_t)arow        * EMB;
    const float* bptr = Wx_w + (size_t)(col0 + lr) * EMB;

    float acc[8][8];
#pragma unroll
    for (int i = 0; i < 8; i++)
#pragma unroll
        for (int j = 0; j < 8; j++) acc[i][j] = 0.0f;

    float4 pa = *(const float4*)(aptr + lc);
    float4 pb = *(const float4*)(bptr + lc);

    for (int k0 = 0; k0 < EMB; k0 += 8) {
        __syncthreads();
        As[lc + 0][lr] = pa.x; As[lc + 1][lr] = pa.y;
        As[lc + 2][lr] = pa.z; As[lc + 3][lr] = pa.w;
        Bs[lc + 0][lr] = pb.x; Bs[lc + 1][lr] = pb.y;
        Bs[lc + 2][lr] = pb.z; Bs[lc + 3][lr] = pb.w;
        __syncthreads();

        if (k0 + 8 < EMB) {
            pa = *(const float4*)(aptr + k0 + 8 + lc);
            pb = *(const float4*)(bptr + k0 + 8 + lc);
        }

#pragma unroll
        for (int k = 0; k < 8; k++) {
            float ra[8], rb[8];
#pragma unroll
            for (int i = 0; i < 8; i++) ra[i] = As[k][ty * 8 + i];
#pragma unroll
            for (int j = 0; j < 8; j++) rb[j] = Bs[k][tx * 8 + j];
#pragma unroll
            for (int i = 0; i < 8; i++)
#pragma unroll
                for (int j = 0; j < 8; j++) acc[i][j] += ra[i] * rb[j];
        }
    }

#pragma unroll
    for (int i = 0; i < 8; i++) {
        int m = row0 + ty * 8 + i;
        float* op = g_xproj + (size_t)m * HID + col0 + tx * 8;
#pragma unroll
        for (int j = 0; j < 8; j++) {
            int n = col0 + tx * 8 + j;
            op[j] = acc[i][j] + Wx_b[n] + Wh_b[n];
        }
    }
}

// ---------------------------------------------------------------------------
// Cluster-based persistent scan, 512 threads (16 warps) per CTA.
// 16 clusters x 8 CTAs. Cluster = 4 batch rows; rank = 64-column j-slice.
// Wh slice in smem; full h double-buffered in every rank's smem, exchanged
// per step via DSMEM float4 stores + cluster.sync.
// Thread layout phase A: 8 k-slices (64 k each) x 64 j-lanes.
// ---------------------------------------------------------------------------
#define SW_PAD 65
#define SCAN_SMEM_FLOATS (512 * SW_PAD + 2 * 512 * 4 + 8 * 4 * 64)
#define SCAN_SMEM_BYTES  (SCAN_SMEM_FLOATS * 4)   // 157,696 B

__global__ __launch_bounds__(512, 1) __cluster_dims__(8, 1, 1)
void scan_kernel(const float* __restrict__ Wh_w,
                 const float* __restrict__ tau) {
    extern __shared__ float smem[];
    float* sw   = smem;                      // [512 k][65]   Wh slice (transposed)
    float* sh   = smem + 512 * SW_PAD;       // [2][512 k][4 b] h double buffer
    float* sred = sh + 2 * 512 * 4;          // [8 ks][4 b][64 jl]

    cg::cluster_group cluster = cg::this_cluster();
    const int rank = (int)cluster.block_rank();   // 0..7 -> j slice
    const int cid  = blockIdx.x >> 3;             // 0..15 -> batch slice
    const int tid  = threadIdx.x;
    const int j0   = rank * 64;
    const int b0   = cid * 4;

    // ---- load Wh slice transposed into smem: sw[k][jl] = Wh[j0+jl][k] ----
    {
        const int jl = tid & 63;
        const int kq = tid >> 6;                  // 0..7 -> 64-k chunk
        const float* wrow = Wh_w + (size_t)(j0 + jl) * HID + kq * 64;
#pragma unroll
        for (int p = 0; p < 16; p++) {
            float4 wv = *(const float4*)(wrow + p * 4);
            int k4 = kq * 64 + p * 4;
            sw[(k4 + 0) * SW_PAD + jl] = wv.x;
            sw[(k4 + 1) * SW_PAD + jl] = wv.y;
            sw[(k4 + 2) * SW_PAD + jl] = wv.z;
            sw[(k4 + 3) * SW_PAD + jl] = wv.w;
        }
    }
    // ---- zero h buffer 0 ----
    for (int i = tid; i < 512 * 4; i += 512) sh[i] = 0.0f;

    const int jl  = tid & 63;                // column lane
    const int ks  = tid >> 6;                // k-slice 0..7 (phase A)
    const int b_o = (tid >> 6) & 3;          // batch row (phase B, tid<256)
    const float itau = 1.0f / tau[j0 + jl];

    // phase C mapping: 448 threads, one float4 remote store each
    const int pc_row = tid & 63;
    int pc_rk = tid >> 6;                    // 0..6 for tid<448
    if (pc_rk >= rank) pc_rk += 1;           // skip own rank

    __syncthreads();
    cluster.sync();

    for (int s = 0; s < SEQ; s++) {
        const float* shc = sh + (s & 1) * 2048;
        float*       shn = sh + ((s + 1) & 1) * 2048;

        // prefetch xp for this step (consumed in phase B, tid<256 only)
        float xp = 0.0f;
        if (tid < 256)
            xp = __ldcg(&g_xproj[((size_t)(b0 + b_o) * SEQ + s) * HID + j0 + jl]);

        // ---- phase A: partial GEMM over this thread's 64-k slice ----
        unsigned long long acc01 = 0ull, acc23 = 0ull;
        const float* wp = sw + (ks * 64) * SW_PAD + jl;
        const float* hp = shc + ks * 64 * 4;
#pragma unroll 8
        for (int kk = 0; kk < 64; kk++) {
            float w = wp[kk * SW_PAD];
            unsigned wu = __float_as_uint(w);
            unsigned long long ww;
            asm("mov.b64 %0, {%1, %1};" : "=l"(ww) : "r"(wu));
            ulonglong2 h2 = *(const ulonglong2*)(hp + kk * 4);  // broadcast
            asm("fma.rn.f32x2 %0, %1, %2, %0;" : "+l"(acc01) : "l"(h2.x), "l"(ww));
            asm("fma.rn.f32x2 %0, %1, %2, %0;" : "+l"(acc23) : "l"(h2.y), "l"(ww));
        }
        {
            unsigned a0, a1, a2, a3;
            asm("mov.b64 {%0, %1}, %2;" : "=r"(a0), "=r"(a1) : "l"(acc01));
            asm("mov.b64 {%0, %1}, %2;" : "=r"(a2), "=r"(a3) : "l"(acc23));
            float* rp = sred + ks * 256 + jl;
            rp[0]   = __uint_as_float(a0);
            rp[64]  = __uint_as_float(a1);
            rp[128] = __uint_as_float(a2);
            rp[192] = __uint_as_float(a3);
        }
        __syncthreads();

        // ---- phase B (tid<256): reduce 8 k-slices, LTC cell update ----
        if (tid < 256) {
            float sum = 0.f;
#pragma unroll
            for (int k2 = 0; k2 < 8; k2++) sum += sred[k2 * 256 + b_o * 64 + jl];
            float z    = sum + xp;
            float th   = tanhf(z);
            float hold = shc[(j0 + jl) * 4 + b_o];
            float hn   = hold + (th - hold) * itau;

            g_hs[((size_t)(b0 + b_o) * SEQ + s) * HID + j0 + jl] = hn;
            shn[(j0 + jl) * 4 + b_o] = hn;     // own slice of next-h, local
        }
        __syncthreads();

        // ---- phase C: broadcast own 64-row h slice to the 7 peers ----
        if (s < SEQ - 1) {
            if (tid < 448) {
                float4* src = (float4*)&shn[(j0 + pc_row) * 4];
                float4  v   = *src;
                float4* dst = cluster.map_shared_rank(src, pc_rk);
                *dst = v;
            }
            cluster.sync();
        }
    }
}

// ---------------------------------------------------------------------------
// Output GEMM + sigmoid: y[m][c] = sigmoid(sum_h hs[m][h]*Wo_w[c][h] + Wo_b[c])
// ---------------------------------------------------------------------------
__global__ __launch_bounds__(256, 2)
void out_kernel(const float* __restrict__ Wo_w,
                const float* __restrict__ Wo_b,
                float* __restrict__ out) {
    __shared__ float As[8][128];
    __shared__ float Bs[8][128];

    const int tid  = threadIdx.x;
    const int row0 = blockIdx.y * 128;
    const int col0 = blockIdx.x * 128;

    const int lr = tid >> 1;
    const int lc = (tid & 1) * 4;
    const int tx = tid & 15;
    const int ty = tid >> 4;

    const float* aptr = g_hs + (size_t)(row0 + lr) * HID;
    const float* bptr = Wo_w + (size_t)(col0 + lr) * HID;

    float acc[8][8];
#pragma unroll
    for (int i = 0; i < 8; i++)
#pragma unroll
        for (int j = 0; j < 8; j++) acc[i][j] = 0.0f;

    float4 pa = *(const float4*)(aptr + lc);
    float4 pb = *(const float4*)(bptr + lc);

    for (int k0 = 0; k0 < HID; k0 += 8) {
        __syncthreads();
        As[lc + 0][lr] = pa.x; As[lc + 1][lr] = pa.y;
        As[lc + 2][lr] = pa.z; As[lc + 3][lr] = pa.w;
        Bs[lc + 0][lr] = pb.x; Bs[lc + 1][lr] = pb.y;
        Bs[lc + 2][lr] = pb.z; Bs[lc + 3][lr] = pb.w;
        __syncthreads();

        if (k0 + 8 < HID) {
            pa = *(const float4*)(aptr + k0 + 8 + lc);
            pb = *(const float4*)(bptr + k0 + 8 + lc);
        }

#pragma unroll
        for (int k = 0; k < 8; k++) {
            float ra[8], rb[8];
#pragma unroll
            for (int i = 0; i < 8; i++) ra[i] = As[k][ty * 8 + i];
#pragma unroll
            for (int j = 0; j < 8; j++) rb[j] = Bs[k][tx * 8 + j];
#pragma unroll
            for (int i = 0; i < 8; i++)
#pragma unroll
                for (int j = 0; j < 8; j++) acc[i][j] += ra[i] * rb[j];
        }
    }

#pragma unroll
    for (int i = 0; i < 8; i++) {
        int m = row0 + ty * 8 + i;
        float* op = out + (size_t)m * NUM_C + col0 + tx * 8;
#pragma unroll
        for (int j = 0; j < 8; j++) {
            int n = col0 + tx * 8 + j;
            float logit = acc[i][j] + Wo_b[n];
            op[j] = 1.0f / (1.0f + expf(-logit));
        }
    }
}

// ---------------------------------------------------------------------------
extern "C" void kernel_launch(void* const* d_in, const int* in_sizes, int n_in,
                              void* d_out, int out_size) {
    const int*   q    = (const int*)  d_in[0];
    const int*   r    = (const int*)  d_in[1];
    const float* emb  = (const float*)d_in[2];
    const float* Wh_w = (const float*)d_in[3];
    const float* Wh_b = (const float*)d_in[4];
    const float* Wx_w = (const float*)d_in[5];
    const float* Wx_b = (const float*)d_in[6];
    const float* tau  = (const float*)d_in[7];
    const float* Wo_w = (const float*)d_in[8];
    const float* Wo_b = (const float*)d_in[9];
    float*       out  = (float*)d_out;

    // idempotent, capture-legal
    cudaFuncSetAttribute(scan_kernel,
                         cudaFuncAttributeMaxDynamicSharedMemorySize,
                         SCAN_SMEM_BYTES);

    // 1) input projection GEMM (gather fused)
    {
        dim3 grid(HID / 128, M_ROWS / 128);
        xproj_kernel<<<grid, 256>>>(q, r, emb, Wx_w, Wx_b, Wh_b);
    }
    // 2) cluster scan: 128 CTAs = 16 clusters x 8 ranks, 512 threads
    scan_kernel<<<128, 512, SCAN_SMEM_BYTES>>>(Wh_w, tau);
    // 3) output GEMM + sigmoid
    {
        dim3 grid(NUM_C / 128, M_ROWS / 128);
        out_kernel<<<grid, 256>>>(Wo_w, Wo_b, out);
    }
}

// round 5
// speedup vs baseline: 1.2417x; 1.2417x over previous
#include <cuda_runtime.h>
#include <cuda_bf16.h>
#include <cooperative_groups.h>
#include <cstdint>

namespace cg = cooperative_groups;

#define NUM_C 1024
#define EMB   512
#define HID   512
#define BATCH 64
#define SEQ   512
#define M_ROWS (BATCH * SEQ)   // 32768
#define NROWS 2048             // distinct embedding rows

// ---------------------------------------------------------------------------
// Device scratch
// ---------------------------------------------------------------------------
__device__ float g_table[(size_t)NROWS * HID];    // 4 MB: emb@Wx^T + bx + bh
__device__ float g_hs   [(size_t)M_ROWS * HID];   // 64 MB: scan outputs

// ---------------------------------------------------------------------------
// f32x2 helpers
// ---------------------------------------------------------------------------
__device__ __forceinline__ void fma2(unsigned long long& acc,
                                     unsigned long long a, unsigned long long b) {
    asm("fma.rn.f32x2 %0, %1, %2, %0;" : "+l"(acc) : "l"(a), "l"(b));
}
__device__ __forceinline__ unsigned long long pk2(float lo, float hi) {
    unsigned long long r;
    asm("mov.b64 %0, {%1, %2};" : "=l"(r) : "f"(lo), "f"(hi));
    return r;
}
__device__ __forceinline__ unsigned long long dup2(float x) {
    unsigned long long r;
    asm("mov.b64 %0, {%1, %1};" : "=l"(r) : "f"(x));
    return r;
}
__device__ __forceinline__ void upk2(unsigned long long v, float& lo, float& hi) {
    asm("mov.b64 {%0, %1}, %2;" : "=f"(lo), "=f"(hi) : "l"(v));
}
__device__ __forceinline__ void add2(unsigned long long& acc, unsigned long long a) {
    asm("add.rn.f32x2 %0, %1, %2;" : "=l"(acc) : "l"(acc), "l"(a));
}

// ---------------------------------------------------------------------------
// proj table GEMM: table[m][n] = sum_e emb[m][e]*Wx_w[n][e] + Wx_b[n] + Wh_b[n]
// M=2048, N=512, K=512. 128x128 tile, f32x2 inner.
// ---------------------------------------------------------------------------
__global__ __launch_bounds__(256, 2)
void proj_kernel(const float* __restrict__ emb,
                 const float* __restrict__ Wx_w,
                 const float* __restrict__ Wx_b,
                 const float* __restrict__ Wh_b) {
    __shared__ float As[8][128];
    __shared__ float Bs[8][128];

    const int tid  = threadIdx.x;
    const int row0 = blockIdx.y * 128;
    const int col0 = blockIdx.x * 128;

    const int lr = tid >> 1;
    const int lc = (tid & 1) * 4;
    const int tx = tid & 15;
    const int ty = tid >> 4;

    const float* aptr = emb  + (size_t)(row0 + lr) * EMB;
    const float* bptr = Wx_w + (size_t)(col0 + lr) * EMB;

    unsigned long long accp[8][4];
#pragma unroll
    for (int i = 0; i < 8; i++)
#pragma unroll
        for (int j = 0; j < 4; j++) accp[i][j] = 0ull;

    float4 pa = *(const float4*)(aptr + lc);
    float4 pb = *(const float4*)(bptr + lc);

    for (int k0 = 0; k0 < EMB; k0 += 8) {
        __syncthreads();
        As[lc + 0][lr] = pa.x; As[lc + 1][lr] = pa.y;
        As[lc + 2][lr] = pa.z; As[lc + 3][lr] = pa.w;
        Bs[lc + 0][lr] = pb.x; Bs[lc + 1][lr] = pb.y;
        Bs[lc + 2][lr] = pb.z; Bs[lc + 3][lr] = pb.w;
        __syncthreads();

        if (k0 + 8 < EMB) {
            pa = *(const float4*)(aptr + k0 + 8 + lc);
            pb = *(const float4*)(bptr + k0 + 8 + lc);
        }

#pragma unroll
        for (int k = 0; k < 8; k++) {
            float4 a0 = *(const float4*)&As[k][ty * 8];
            float4 a1 = *(const float4*)&As[k][ty * 8 + 4];
            float4 b0 = *(const float4*)&Bs[k][tx * 8];
            float4 b1 = *(const float4*)&Bs[k][tx * 8 + 4];
            unsigned long long bp0 = pk2(b0.x, b0.y), bp1 = pk2(b0.z, b0.w);
            unsigned long long bp2 = pk2(b1.x, b1.y), bp3 = pk2(b1.z, b1.w);
            float av[8] = {a0.x, a0.y, a0.z, a0.w, a1.x, a1.y, a1.z, a1.w};
#pragma unroll
            for (int i = 0; i < 8; i++) {
                unsigned long long ad = dup2(av[i]);
                fma2(accp[i][0], ad, bp0);
                fma2(accp[i][1], ad, bp1);
                fma2(accp[i][2], ad, bp2);
                fma2(accp[i][3], ad, bp3);
            }
        }
    }

#pragma unroll
    for (int i = 0; i < 8; i++) {
        int m = row0 + ty * 8 + i;
        float* op = g_table + (size_t)m * HID + col0 + tx * 8;
#pragma unroll
        for (int jp = 0; jp < 4; jp++) {
            float v0, v1;
            upk2(accp[i][jp], v0, v1);
            int n = col0 + tx * 8 + jp * 2;
            op[jp * 2]     = v0 + Wx_b[n]     + Wh_b[n];
            op[jp * 2 + 1] = v1 + Wx_b[n + 1] + Wh_b[n + 1];
        }
    }
}

// ---------------------------------------------------------------------------
// Cluster scan. 16 clusters x 8 CTAs; CTA = 64 j x 4 b; 512 threads.
// Wh in REGISTERS (f32x2 j-pairs). h in smem duplicated [k][b](h,h).
// Phase A thread: jg = tid&15 (4 j), ks = tid>>4 (16 k). 10 insts / 16 MACs.
// ---------------------------------------------------------------------------
// smem floats: sh2 2*512*8 = 8192 | sredp 32*4*32 u64 = 8192 | sidx 2048 ints
#define SCAN_SMEM_FLOATS (8192 + 8192 + 2048)
#define SCAN_SMEM_BYTES  (SCAN_SMEM_FLOATS * 4)   // 73,728 B

__global__ __launch_bounds__(512, 1) __cluster_dims__(8, 1, 1)
void scan_kernel(const int* __restrict__ q, const int* __restrict__ r,
                 const float* __restrict__ Wh_w,
                 const float* __restrict__ tau) {
    extern __shared__ float smem[];
    float*              sh2   = smem;                                  // [2][512][8]
    unsigned long long* srp   = (unsigned long long*)(smem + 8192);    // [32ks][4b][32jp]
    int*                sidxm = (int*)(smem + 16384);                  // [4b][512s]

    cg::cluster_group cluster = cg::this_cluster();
    const int rank = (int)cluster.block_rank();
    const int cid  = blockIdx.x >> 3;
    const int tid  = threadIdx.x;
    const int j0   = rank * 64;
    const int b0   = cid * 4;

    // ---- stage idx table: sidxm[b][s] ----
    for (int i = tid; i < 4 * SEQ; i += 512) {
        int b = i >> 9, s = i & 511;
        int m = (b0 + b) * SEQ + s;
        sidxm[i] = q[m] + NUM_C * r[m];
    }
    // ---- zero h buffer 0 ----
    for (int i = tid; i < 4096; i += 512) sh2[i] = 0.0f;

    // ---- phase A mapping + register-resident Wh ----
    const int jg = tid & 15;            // 4-j group
    const int ks = tid >> 4;            // 16-k slice, 0..31
    const int jA = j0 + jg * 4;
    const int sx = (ks & 1) * 2;        // b-pair swap parity
    const int swo = (ks & 1) * 4;       // float offset for conflict-free loads

    unsigned long long w2[2][16];
    {
        const float* r0 = Wh_w + (size_t)(jA + 0) * HID + ks * 16;
        const float* r1 = Wh_w + (size_t)(jA + 1) * HID + ks * 16;
        const float* r2 = Wh_w + (size_t)(jA + 2) * HID + ks * 16;
        const float* r3 = Wh_w + (size_t)(jA + 3) * HID + ks * 16;
#pragma unroll
        for (int t = 0; t < 4; t++) {
            float4 f0 = *(const float4*)(r0 + t * 4);
            float4 f1 = *(const float4*)(r1 + t * 4);
            float4 f2 = *(const float4*)(r2 + t * 4);
            float4 f3 = *(const float4*)(r3 + t * 4);
            const float* p0 = (const float*)&f0;
            const float* p1 = (const float*)&f1;
            const float* p2 = (const float*)&f2;
            const float* p3 = (const float*)&f3;
#pragma unroll
            for (int e = 0; e < 4; e++) {
                w2[0][t * 4 + e] = pk2(p0[e], p1[e]);
                w2[1][t * 4 + e] = pk2(p2[e], p3[e]);
            }
        }
    }

    // ---- phase B mapping ----
    const int jp_b = tid & 31;          // j-pair 0..31 (j = 2jp, 2jp+1)
    const int b_b  = (tid >> 5) & 3;    // batch row (tid<128)
    float it0 = 1.0f, it1 = 1.0f;
    if (tid < 128) {
        it0 = 1.0f / tau[j0 + 2 * jp_b];
        it1 = 1.0f / tau[j0 + 2 * jp_b + 1];
    }

    __syncthreads();
    cluster.sync();

    for (int s = 0; s < SEQ; s++) {
        const float* shc = sh2 + (s & 1) * 4096;
        float*       shn = sh2 + ((s + 1) & 1) * 4096;

        // phase-B prefetch: xp (from L2-resident table) + hold
        float xp0 = 0.f, xp1 = 0.f, hold0 = 0.f, hold1 = 0.f;
        if (tid < 128) {
            int row = sidxm[b_b * SEQ + s];
            float2 xp2 = *(const float2*)&g_table[(size_t)row * HID + j0 + 2 * jp_b];
            xp0 = xp2.x; xp1 = xp2.y;
            hold0 = shc[(j0 + 2 * jp_b) * 8 + b_b * 2];
            hold1 = shc[(j0 + 2 * jp_b + 1) * 8 + b_b * 2];
        }

        // ---- phase A ----
        unsigned long long acc[2][4];
#pragma unroll
        for (int jp = 0; jp < 2; jp++)
#pragma unroll
            for (int bb = 0; bb < 4; bb++) acc[jp][bb] = 0ull;

        const float* hp = shc + (ks * 16) * 8;
#pragma unroll
        for (int kk = 0; kk < 16; kk++) {
            ulonglong2 u = *(const ulonglong2*)(hp + kk * 8 + swo);
            ulonglong2 v = *(const ulonglong2*)(hp + kk * 8 + 4 - swo);
            fma2(acc[0][0], w2[0][kk], u.x);
            fma2(acc[0][1], w2[0][kk], u.y);
            fma2(acc[0][2], w2[0][kk], v.x);
            fma2(acc[0][3], w2[0][kk], v.y);
            fma2(acc[1][0], w2[1][kk], u.x);
            fma2(acc[1][1], w2[1][kk], u.y);
            fma2(acc[1][2], w2[1][kk], v.x);
            fma2(acc[1][3], w2[1][kk], v.y);
        }
        {
            const int jpg = jg * 2;
#pragma unroll
            for (int bb = 0; bb < 4; bb++) {
                int b = bb ^ sx;   // undo parity swap
                srp[(ks * 4 + b) * 32 + jpg]     = acc[0][bb];
                srp[(ks * 4 + b) * 32 + jpg + 1] = acc[1][bb];
            }
        }
        __syncthreads();

        // ---- phase B (tid<128): reduce 32 k-slices, LTC update ----
        if (tid < 128) {
            unsigned long long s2 = srp[(0 * 4 + b_b) * 32 + jp_b];
#pragma unroll
            for (int k2 = 1; k2 < 32; k2++)
                add2(s2, srp[(k2 * 4 + b_b) * 32 + jp_b]);
            float f0, f1;
            upk2(s2, f0, f1);
            float th0 = tanhf(f0 + xp0);
            float th1 = tanhf(f1 + xp1);
            float hn0 = hold0 + (th0 - hold0) * it0;
            float hn1 = hold1 + (th1 - hold1) * it1;

            *(float2*)&g_hs[((size_t)(b0 + b_b) * SEQ + s) * HID + j0 + 2 * jp_b]
                = make_float2(hn0, hn1);
            *(float2*)&shn[(j0 + 2 * jp_b) * 8 + b_b * 2]     = make_float2(hn0, hn0);
            *(float2*)&shn[(j0 + 2 * jp_b + 1) * 8 + b_b * 2] = make_float2(hn1, hn1);
        }
        __syncthreads();

        // ---- phase C: broadcast own 64-row dup slice (2KB) to 7 peers ----
        if (s < SEQ - 1) {
            for (int idx = tid; idx < 896; idx += 512) {
                int rk_i = idx >> 7;
                int rem  = idx & 127;
                int rk   = rk_i + (rk_i >= rank);
                float4* src = (float4*)(shn + (j0 + (rem >> 1)) * 8 + (rem & 1) * 4);
                float4  v   = *src;
                float4* dst = cluster.map_shared_rank(src, rk);
                *dst = v;
            }
            cluster.sync();
        }
    }
}

// ---------------------------------------------------------------------------
// Output GEMM + sigmoid (f32x2 inner)
// ---------------------------------------------------------------------------
__global__ __launch_bounds__(256, 2)
void out_kernel(const float* __restrict__ Wo_w,
                const float* __restrict__ Wo_b,
                float* __restrict__ out) {
    __shared__ float As[8][128];
    __shared__ float Bs[8][128];

    const int tid  = threadIdx.x;
    const int row0 = blockIdx.y * 128;
    const int col0 = blockIdx.x * 128;

    const int lr = tid >> 1;
    const int lc = (tid & 1) * 4;
    const int tx = tid & 15;
    const int ty = tid >> 4;

    const float* aptr = g_hs + (size_t)(row0 + lr) * HID;
    const float* bptr = Wo_w + (size_t)(col0 + lr) * HID;

    unsigned long long accp[8][4];
#pragma unroll
    for (int i = 0; i < 8; i++)
#pragma unroll
        for (int j = 0; j < 4; j++) accp[i][j] = 0ull;

    float4 pa = *(const float4*)(aptr + lc);
    float4 pb = *(const float4*)(bptr + lc);

    for (int k0 = 0; k0 < HID; k0 += 8) {
        __syncthreads();
        As[lc + 0][lr] = pa.x; As[lc + 1][lr] = pa.y;
        As[lc + 2][lr] = pa.z; As[lc + 3][lr] = pa.w;
        Bs[lc + 0][lr] = pb.x; Bs[lc + 1][lr] = pb.y;
        Bs[lc + 2][lr] = pb.z; Bs[lc + 3][lr] = pb.w;
        __syncthreads();

        if (k0 + 8 < HID) {
            pa = *(const float4*)(aptr + k0 + 8 + lc);
            pb = *(const float4*)(bptr + k0 + 8 + lc);
        }

#pragma unroll
        for (int k = 0; k < 8; k++) {
            float4 a0 = *(const float4*)&As[k][ty * 8];
            float4 a1 = *(const float4*)&As[k][ty * 8 + 4];
            float4 b0 = *(const float4*)&Bs[k][tx * 8];
            float4 b1 = *(const float4*)&Bs[k][tx * 8 + 4];
            unsigned long long bp0 = pk2(b0.x, b0.y), bp1 = pk2(b0.z, b0.w);
            unsigned long long bp2 = pk2(b1.x, b1.y), bp3 = pk2(b1.z, b1.w);
            float av[8] = {a0.x, a0.y, a0.z, a0.w, a1.x, a1.y, a1.z, a1.w};
#pragma unroll
            for (int i = 0; i < 8; i++) {
                unsigned long long ad = dup2(av[i]);
                fma2(accp[i][0], ad, bp0);
                fma2(accp[i][1], ad, bp1);
                fma2(accp[i][2], ad, bp2);
                fma2(accp[i][3], ad, bp3);
            }
        }
    }

#pragma unroll
    for (int i = 0; i < 8; i++) {
        int m = row0 + ty * 8 + i;
        float* op = out + (size_t)m * NUM_C + col0 + tx * 8;
#pragma unroll
        for (int jp = 0; jp < 4; jp++) {
            float v0, v1;
            upk2(accp[i][jp], v0, v1);
            int n = col0 + tx * 8 + jp * 2;
            float l0 = v0 + Wo_b[n];
            float l1 = v1 + Wo_b[n + 1];
            op[jp * 2]     = 1.0f / (1.0f + expf(-l0));
            op[jp * 2 + 1] = 1.0f / (1.0f + expf(-l1));
        }
    }
}

// ---------------------------------------------------------------------------
extern "C" void kernel_launch(void* const* d_in, const int* in_sizes, int n_in,
                              void* d_out, int out_size) {
    const int*   q    = (const int*)  d_in[0];
    const int*   r    = (const int*)  d_in[1];
    const float* emb  = (const float*)d_in[2];
    const float* Wh_w = (const float*)d_in[3];
    const float* Wh_b = (const float*)d_in[4];
    const float* Wx_w = (const float*)d_in[5];
    const float* Wx_b = (const float*)d_in[6];
    const float* tau  = (const float*)d_in[7];
    const float* Wo_w = (const float*)d_in[8];
    const float* Wo_b = (const float*)d_in[9];
    float*       out  = (float*)d_out;

    cudaFuncSetAttribute(scan_kernel,
                         cudaFuncAttributeMaxDynamicSharedMemorySize,
                         SCAN_SMEM_BYTES);

    // 1) projection table: 2048 x 512 (biases folded)
    {
        dim3 grid(HID / 128, NROWS / 128);
        proj_kernel<<<grid, 256>>>(emb, Wx_w, Wx_b, Wh_b);
    }
    // 2) cluster scan
    scan_kernel<<<128, 512, SCAN_SMEM_BYTES>>>(q, r, Wh_w, tau);
    // 3) output GEMM + sigmoid
    {
        dim3 grid(NUM_C / 128, M_ROWS / 128);
        out_kernel<<<grid, 256>>>(Wo_w, Wo_b, out);
    }
}